// round 2
// baseline (speedup 1.0000x reference)
#include <cuda_runtime.h>
#include <math.h>

// ---------------- problem constants ----------------
#define BATCH   4096
#define C1      64
#define IMH     28
#define IMW     28
#define PH      12
#define POS     (PH*PH)         // 144
#define CL      (C1*POS)        // 9216
#define NFC     1024
#define K1K     400
#define KFC     100
#define CAP     512
#define PKS     1024            // packed-value stride per row (worst case)

// ---------------- scratch (static device globals) ----------------
__device__ __align__(16) float          g_Wt[CL * NFC];     // dense masked W^T [j][n]
__device__ __align__(16) float          g_pk[(size_t)CL * PKS]; // packed nonzeros per row
__device__ unsigned int   g_msk[CL * 32];                   // bitmask per row (1024 bits)
__device__ unsigned short g_off[CL * 32];                   // per-word exclusive nz offsets
__device__ float          g_val[BATCH * CAP];
__device__ unsigned short g_idx[BATCH * CAP];
__device__ int            g_cnt[BATCH];

// order-preserving float <-> uint transforms
__device__ __forceinline__ unsigned int f2u(float f) {
    unsigned int u = __float_as_uint(f);
    return (u & 0x80000000u) ? ~u : (u | 0x80000000u);
}
__device__ __forceinline__ float u2f(unsigned int u) {
    unsigned int b = (u & 0x80000000u) ? (u & 0x7fffffffu) : ~u;
    return __uint_as_float(b);
}

// packed f32x2 helpers (Blackwell)
__device__ __forceinline__ unsigned long long pk2(float lo, float hi) {
    unsigned long long r;
    asm("mov.b64 %0, {%1, %2};" : "=l"(r) : "f"(lo), "f"(hi));
    return r;
}
__device__ __forceinline__ unsigned long long dup2(float w) {
    unsigned long long r;
    asm("mov.b64 %0, {%1, %1};" : "=l"(r) : "f"(w));
    return r;
}
__device__ __forceinline__ void ffma2(unsigned long long& d, unsigned long long a,
                                      unsigned long long b) {
    asm("fma.rn.f32x2 %0, %1, %2, %0;" : "+l"(d) : "l"(a), "l"(b));
}
__device__ __forceinline__ void unpk(unsigned long long v, float& lo, float& hi) {
    asm("mov.b64 {%0, %1}, %2;" : "=f"(lo), "=f"(hi) : "l"(v));
}

// ================= K0a: mask + transpose fc1 weights =================
__global__ void k_prep(const float* __restrict__ w, const float* __restrict__ m) {
    __shared__ float tile[32][33];
    int jb = blockIdx.x * 32;
    int nb = blockIdx.y * 32;
    int tx = threadIdx.x, ty = threadIdx.y;   // (32, 8)
#pragma unroll
    for (int r = 0; r < 32; r += 8) {
        int n = nb + ty + r;
        int j = jb + tx;
        float wv = w[n * CL + j];
        float mv = m[n * CL + j];
        tile[ty + r][tx] = (mv < 0.5f) ? wv : 0.0f;
    }
    __syncthreads();
#pragma unroll
    for (int r = 0; r < 32; r += 8) {
        int j = jb + ty + r;
        int n = nb + tx;
        g_Wt[j * NFC + n] = tile[tx][ty + r];
    }
}

// ================= K0b: compress each W^T row (mask + offsets + packed vals) ====
__global__ void k_pack() {
    __shared__ unsigned int s_nib[256];
    __shared__ unsigned int s_word[32];
    __shared__ unsigned short s_off[32];
    int j = blockIdx.x;
    int t = threadIdx.x;

    float4 w = ((const float4*)g_Wt)[j * (NFC / 4) + t];
    unsigned int nib = (w.x != 0.f ? 1u : 0u) | (w.y != 0.f ? 2u : 0u) |
                       (w.z != 0.f ? 4u : 0u) | (w.w != 0.f ? 8u : 0u);
    s_nib[t] = nib;
    __syncthreads();
    if (t < 32) {
        unsigned int word = 0;
#pragma unroll
        for (int q = 0; q < 8; q++) word |= s_nib[t * 8 + q] << (4 * q);
        s_word[t] = word;
        int pc = __popc(word);
        int sc = pc;
#pragma unroll
        for (int d = 1; d < 32; d <<= 1) {
            int o = __shfl_up_sync(0xffffffffu, sc, d);
            if (t >= d) sc += o;
        }
        unsigned short off = (unsigned short)(sc - pc);
        s_off[t] = off;
        g_msk[j * 32 + t] = word;
        g_off[j * 32 + t] = off;
    }
    __syncthreads();
    unsigned int word = s_word[t >> 3];
    int bitpos = (t & 7) * 4;
    int base = (int)s_off[t >> 3] + __popc(word & ((1u << bitpos) - 1u));
    float* dst = g_pk + (size_t)j * PKS;
    if (nib & 1) dst[base++] = w.x;
    if (nib & 2) dst[base++] = w.y;
    if (nib & 4) dst[base++] = w.z;
    if (nib & 8) dst[base++] = w.w;
}

// ================= K1: fused conv + pool + kwinners(400/9216) =================
#define T1 288

__global__ void __launch_bounds__(T1) k_conv_pool_kw(
    const float* __restrict__ x, const float* __restrict__ cw,
    const float* __restrict__ cb, const float* __restrict__ duty)
{
    __shared__ unsigned int s_keys[CL];    // 36 KB: f2u(pooled * boost)
    __shared__ float img[IMH * IMW];       // 3.1 KB
    __shared__ float wts[C1 * 25];         // 6.4 KB
    __shared__ float bias[C1];
    __shared__ float boost[C1];
    __shared__ unsigned int hist[256];
    __shared__ int s_wsum[16];
    __shared__ unsigned int sel_prefix;
    __shared__ int sel_kr;
    __shared__ int sel_total;

    const int tid = threadIdx.x;
    const int b   = blockIdx.x;

    const float* xb = x + b * (IMH * IMW);
    for (int i = tid; i < IMH * IMW; i += T1) img[i] = xb[i];
    for (int i = tid; i < C1 * 25;   i += T1) wts[i] = cw[i];
    if (tid < C1) {
        bias[tid]  = cb[tid];
        boost[tid] = expf(400.0f / 9216.0f - duty[tid]);
    }
    __syncthreads();

    // ---- conv 5x5 + maxpool 2x2 with packed f32x2 FMA ----
    {
        int pos = tid % POS;          // 0..143
        int cg  = tid / POS;          // 0..1
        int py = pos / PH, px = pos % PH;
        int r0 = py * 2, c0 = px * 2;
        // horizontal patch pairs pp[u][v] = {p[u][v], p[u][v+1]}, u=0..5, v=0..4
        unsigned long long pp[30];
#pragma unroll
        for (int u = 0; u < 6; u++) {
            float r[6];
#pragma unroll
            for (int v = 0; v < 6; v++) r[v] = img[(r0 + u) * IMW + (c0 + v)];
#pragma unroll
            for (int v = 0; v < 5; v++) pp[u * 5 + v] = pk2(r[v], r[v + 1]);
        }
        int cbase = cg * 32;
        for (int cc = 0; cc < 32; cc++) {
            int c = cbase + cc;
            const float* wc = wts + c * 25;
            unsigned long long a01 = 0ull, a23 = 0ull;  // {s00,s01}, {s10,s11}
#pragma unroll
            for (int u = 0; u < 5; u++) {
#pragma unroll
                for (int v = 0; v < 5; v++) {
                    unsigned long long w2 = dup2(wc[u * 5 + v]);
                    ffma2(a01, pp[u * 5 + v], w2);
                    ffma2(a23, pp[(u + 1) * 5 + v], w2);
                }
            }
            float s00, s01, s10, s11;
            unpk(a01, s00, s01);
            unpk(a23, s10, s11);
            float m = fmaxf(fmaxf(s00, s01), fmaxf(s10, s11)) + bias[c];
            s_keys[c * POS + pos] = f2u(m * boost[c]);
        }
    }
    __syncthreads();

    // ---- exact k-th largest via 4-pass radix select on keys ----
    if (tid == 0) { sel_prefix = 0u; sel_kr = K1K; }
    __syncthreads();
    for (int shift = 24; shift >= 0; shift -= 8) {
        if (tid < 256) hist[tid] = 0u;
        __syncthreads();
        unsigned int pfx    = sel_prefix;
        unsigned int himask = (shift == 24) ? 0u : (0xFFFFFFFFu << (shift + 8));
        for (int i = tid; i < CL; i += T1) {
            unsigned int u = s_keys[i];
            if ((u & himask) == pfx) atomicAdd(&hist[(u >> shift) & 255], 1u);
        }
        __syncthreads();
        if (tid == 0) {
            int kk = sel_kr; unsigned int acc = 0;
            for (int bin = 255; bin >= 0; --bin) {
                unsigned int h = hist[bin];
                if (acc + h >= (unsigned)kk) {
                    sel_prefix = pfx | ((unsigned)bin << shift);
                    sel_kr = kk - (int)acc;
                    break;
                }
                acc += h;
            }
        }
        __syncthreads();
    }
    unsigned int thr = sel_prefix;

    // ---- deterministic compaction ----
    int mycnt = 0;
    for (int i = tid; i < CL; i += T1)
        if (s_keys[i] >= thr) mycnt++;

    int lane = tid & 31, wrp = tid >> 5;
    int v = mycnt;
#pragma unroll
    for (int d = 1; d < 32; d <<= 1) {
        int t = __shfl_up_sync(0xFFFFFFFFu, v, d);
        if (lane >= d) v += t;
    }
    if (lane == 31) s_wsum[wrp] = v;
    __syncthreads();
    if (tid == 0) {
        int a = 0;
        for (int w = 0; w < T1 / 32; w++) { int t = s_wsum[w]; s_wsum[w] = a; a += t; }
        sel_total = a;
    }
    __syncthreads();
    int off = s_wsum[wrp] + v - mycnt;
    for (int i = tid; i < CL; i += T1) {
        unsigned int k = s_keys[i];
        if (k >= thr) {
            if (off < CAP) {
                g_idx[b * CAP + off] = (unsigned short)i;
                g_val[b * CAP + off] = u2f(k) / boost[i / POS];
            }
            off++;
        }
    }
    if (tid == 0) g_cnt[b] = sel_total > CAP ? CAP : sel_total;
}

// ================= K2: sparse fc1 (compressed W) + kwinners + fc2 + lsm =======
#define T2 256

__global__ void __launch_bounds__(T2) k_fc_out(
    const float* __restrict__ fc1_b, const float* __restrict__ duty_fc,
    const float* __restrict__ w2,    const float* __restrict__ b2,
    float* __restrict__ out)
{
    __shared__ float         s_val[CAP];
    __shared__ int           s_idx[CAP];
    __shared__ float         s_h[NFC];
    __shared__ unsigned int  s_keys[NFC];
    __shared__ unsigned int  hist[256];
    __shared__ unsigned int  sel_prefix;
    __shared__ int           sel_kr;
    __shared__ float         s_red[8][10];
    __shared__ float         s_logits[10];
    __shared__ float         s_lse;

    const int tid = threadIdx.x;
    const int b   = blockIdx.x;

    int cnt = g_cnt[b];
    for (int i = tid; i < cnt; i += T2) {
        s_idx[i] = g_idx[b * CAP + i];
        s_val[i] = g_val[b * CAP + i];
    }
    __syncthreads();

    // compressed sparse accumulate: thread owns neurons 4*tid .. 4*tid+3
    const int word_i  = tid >> 3;
    const int bitpos  = (tid & 7) * 4;
    const unsigned int lowmask = (1u << bitpos) - 1u;
    float a0 = 0.f, a1 = 0.f, a2 = 0.f, a3 = 0.f;
#pragma unroll 4
    for (int e = 0; e < cnt; e++) {
        float vv = s_val[e];
        int   j  = s_idx[e];
        unsigned int mw = __ldg(&g_msk[j * 32 + word_i]);
        int bo          = (int)__ldg(&g_off[j * 32 + word_i]);
        unsigned int nib = (mw >> bitpos) & 15u;
        int base = bo + __popc(mw & lowmask);
        const float* pr = g_pk + (size_t)j * PKS;
        int b0 = base;
        int b1 = b0 + (int)(nib & 1u);
        int b2 = b1 + (int)((nib >> 1) & 1u);
        int b3 = b2 + (int)((nib >> 2) & 1u);
        if (nib & 1u) a0 = fmaf(vv, __ldg(&pr[b0]), a0);
        if (nib & 2u) a1 = fmaf(vv, __ldg(&pr[b1]), a1);
        if (nib & 4u) a2 = fmaf(vv, __ldg(&pr[b2]), a2);
        if (nib & 8u) a3 = fmaf(vv, __ldg(&pr[b3]), a3);
    }

    const float kdn = 100.0f / 1024.0f;
    {
        int n = tid * 4;
        float h0 = a0 + fc1_b[n],     h1 = a1 + fc1_b[n + 1];
        float h2 = a2 + fc1_b[n + 2], h3 = a3 + fc1_b[n + 3];
        s_h[n] = h0; s_h[n + 1] = h1; s_h[n + 2] = h2; s_h[n + 3] = h3;
        s_keys[n]     = f2u(h0 * expf(kdn - duty_fc[n]));
        s_keys[n + 1] = f2u(h1 * expf(kdn - duty_fc[n + 1]));
        s_keys[n + 2] = f2u(h2 * expf(kdn - duty_fc[n + 2]));
        s_keys[n + 3] = f2u(h3 * expf(kdn - duty_fc[n + 3]));
    }
    __syncthreads();

    // radix select: exact 100th largest boosted h
    if (tid == 0) { sel_prefix = 0u; sel_kr = KFC; }
    __syncthreads();
    for (int shift = 24; shift >= 0; shift -= 8) {
        hist[tid] = 0u;
        __syncthreads();
        unsigned int pfx    = sel_prefix;
        unsigned int himask = (shift == 24) ? 0u : (0xFFFFFFFFu << (shift + 8));
#pragma unroll
        for (int q = 0; q < 4; q++) {
            unsigned int u = s_keys[tid * 4 + q];
            if ((u & himask) == pfx) atomicAdd(&hist[(u >> shift) & 255], 1u);
        }
        __syncthreads();
        if (tid == 0) {
            int kk = sel_kr; unsigned int acc = 0;
            for (int bin = 255; bin >= 0; --bin) {
                unsigned int h = hist[bin];
                if (acc + h >= (unsigned)kk) {
                    sel_prefix = pfx | ((unsigned)bin << shift);
                    sel_kr = kk - (int)acc;
                    break;
                }
                acc += h;
            }
        }
        __syncthreads();
    }
    unsigned int thr = sel_prefix;

    // fc2 over winners
    float part[10];
#pragma unroll
    for (int c = 0; c < 10; c++) part[c] = 0.f;
#pragma unroll
    for (int q = 0; q < 4; q++) {
        int n = tid * 4 + q;
        if (s_keys[n] >= thr) {
            float hv = s_h[n];
#pragma unroll
            for (int c = 0; c < 10; c++)
                part[c] = fmaf(hv, w2[c * NFC + n], part[c]);
        }
    }
    int lane = tid & 31, wrp = tid >> 5;
#pragma unroll
    for (int c = 0; c < 10; c++) {
        float pv = part[c];
#pragma unroll
        for (int d = 16; d > 0; d >>= 1)
            pv += __shfl_down_sync(0xFFFFFFFFu, pv, d);
        if (lane == 0) s_red[wrp][c] = pv;
    }
    __syncthreads();
    if (tid < 10) {
        float s = 0.f;
#pragma unroll
        for (int w = 0; w < 8; w++) s += s_red[w][tid];
        s_logits[tid] = s + b2[tid];
    }
    __syncthreads();
    if (tid == 0) {
        float mx = s_logits[0];
        for (int c = 1; c < 10; c++) mx = fmaxf(mx, s_logits[c]);
        float se = 0.f;
        for (int c = 0; c < 10; c++) se += expf(s_logits[c] - mx);
        s_lse = mx + logf(se);
    }
    __syncthreads();
    if (tid < 10) out[b * 10 + tid] = s_logits[tid] - s_lse;
}

// ================= launch =================
extern "C" void kernel_launch(void* const* d_in, const int* in_sizes, int n_in,
                              void* d_out, int out_size)
{
    const float* x        = (const float*)d_in[0];
    const float* c1_w     = (const float*)d_in[1];
    const float* c1_b     = (const float*)d_in[2];
    const float* duty_cnn = (const float*)d_in[3];
    const float* fc1_w    = (const float*)d_in[4];
    const float* fc1_mask = (const float*)d_in[5];
    const float* fc1_b    = (const float*)d_in[6];
    const float* duty_fc  = (const float*)d_in[7];
    const float* fc2_w    = (const float*)d_in[8];
    const float* fc2_b    = (const float*)d_in[9];
    float* out = (float*)d_out;

    k_prep<<<dim3(CL / 32, NFC / 32), dim3(32, 8)>>>(fc1_w, fc1_mask);
    k_pack<<<CL, 256>>>();
    k_conv_pool_kw<<<BATCH, T1>>>(x, c1_w, c1_b, duty_cnn);
    k_fc_out<<<BATCH, T2>>>(fc1_b, duty_fc, fc2_w, fc2_b, out);
}

// round 3
// speedup vs baseline: 1.7769x; 1.7769x over previous
#include <cuda_runtime.h>
#include <cuda_fp16.h>
#include <math.h>

// ---------------- problem constants ----------------
#define BATCH   4096
#define C1      64
#define IMH     28
#define IMW     28
#define PH      12
#define POS     (PH*PH)         // 144
#define CL      (C1*POS)        // 9216
#define NFC     1024
#define K1K     400
#define KFC     100
#define CAP     512

// ---------------- scratch (static device globals) ----------------
__device__ __align__(16) __half g_Wh[CL * NFC];   // masked fc1_w^T in fp16 [j][n], 18.9 MB
__device__ float          g_val[BATCH * CAP];
__device__ unsigned short g_idx[BATCH * CAP];
__device__ int            g_cnt[BATCH];

// order-preserving float -> uint transform
__device__ __forceinline__ unsigned int f2u(float f) {
    unsigned int u = __float_as_uint(f);
    return (u & 0x80000000u) ? ~u : (u | 0x80000000u);
}

// ================= K0: mask + transpose + fp16-convert fc1 weights ============
__global__ void k_prep(const float* __restrict__ w, const float* __restrict__ m) {
    __shared__ float tile[32][33];
    int jb = blockIdx.x * 32;     // along j (9216)
    int nb = blockIdx.y * 32;     // along n (1024)
    int tx = threadIdx.x, ty = threadIdx.y;   // (32, 8)
#pragma unroll
    for (int r = 0; r < 32; r += 8) {
        int n = nb + ty + r;
        int j = jb + tx;
        float wv = w[n * CL + j];
        float mv = m[n * CL + j];
        tile[ty + r][tx] = (mv < 0.5f) ? wv : 0.0f;
    }
    __syncthreads();
#pragma unroll
    for (int r = 0; r < 32; r += 8) {
        int j = jb + ty + r;
        int n = nb + tx;
        g_Wh[j * NFC + n] = __float2half(tile[tx][ty + r]);
    }
}

// ================= K1: fused conv + pool + kwinners(400/9216) =================
#define T1 288   // 2 channel-groups x 144 positions; 9 warps

__global__ void __launch_bounds__(T1) k_conv_pool_kw(
    const float* __restrict__ x, const float* __restrict__ cw,
    const float* __restrict__ cb, const float* __restrict__ duty)
{
    __shared__ float img[IMH * IMW];       // 784
    __shared__ float wts[C1 * 25];         // 1600
    __shared__ float bias[C1];
    __shared__ float boost[C1];
    __shared__ float pooled[CL];           // 9216 (36 KB)
    __shared__ unsigned int hist[256];
    __shared__ int s_wsum[16];
    __shared__ unsigned int sel_prefix;
    __shared__ int sel_kr;
    __shared__ int sel_total;

    const int tid = threadIdx.x;
    const int b   = blockIdx.x;

    const float* xb = x + b * (IMH * IMW);
    for (int i = tid; i < IMH * IMW; i += T1) img[i] = xb[i];
    for (int i = tid; i < C1 * 25;   i += T1) wts[i] = cw[i];
    if (tid < C1) {
        bias[tid]  = cb[tid];
        boost[tid] = expf(400.0f / 9216.0f - duty[tid]);   // boostStrength = 1
    }
    __syncthreads();

    // ---- conv 5x5 + maxpool 2x2, channel-inner loop, patch in registers ----
    {
        int pos = tid % POS;          // 0..143
        int cg  = tid / POS;          // 0..1
        int py = pos / PH, px = pos % PH;
        int r0 = py * 2, c0 = px * 2;
        float p[36];
#pragma unroll
        for (int u = 0; u < 6; u++)
#pragma unroll
            for (int v = 0; v < 6; v++)
                p[u * 6 + v] = img[(r0 + u) * IMW + (c0 + v)];
        int cbase = cg * 32;
        for (int cc = 0; cc < 32; cc++) {
            int c = cbase + cc;
            const float* wc = wts + c * 25;
            float s00 = 0.f, s01 = 0.f, s10 = 0.f, s11 = 0.f;
#pragma unroll
            for (int u = 0; u < 5; u++) {
#pragma unroll
                for (int v = 0; v < 5; v++) {
                    float wv = wc[u * 5 + v];
                    s00 = fmaf(p[u * 6 + v],     wv, s00);
                    s01 = fmaf(p[u * 6 + v + 1], wv, s01);
                    s10 = fmaf(p[u * 6 + 6 + v], wv, s10);
                    s11 = fmaf(p[u * 6 + 7 + v], wv, s11);
                }
            }
            pooled[c * POS + pos] =
                fmaxf(fmaxf(s00, s01), fmaxf(s10, s11)) + bias[c];
        }
    }
    __syncthreads();

    // ---- exact k-th largest of boosted values via 4-pass radix select ----
    if (tid == 0) { sel_prefix = 0u; sel_kr = K1K; }
    __syncthreads();
    for (int shift = 24; shift >= 0; shift -= 8) {
        if (tid < 256) hist[tid] = 0u;
        __syncthreads();
        unsigned int pfx    = sel_prefix;
        unsigned int himask = (shift == 24) ? 0u : (0xFFFFFFFFu << (shift + 8));
        for (int i = tid; i < CL; i += T1) {
            unsigned int u = f2u(pooled[i] * boost[i / POS]);
            if ((u & himask) == pfx) atomicAdd(&hist[(u >> shift) & 255], 1u);
        }
        __syncthreads();
        if (tid == 0) {
            int kk = sel_kr; unsigned int acc = 0;
            for (int bin = 255; bin >= 0; --bin) {
                unsigned int h = hist[bin];
                if (acc + h >= (unsigned)kk) {
                    sel_prefix = pfx | ((unsigned)bin << shift);
                    sel_kr = kk - (int)acc;
                    break;
                }
                acc += h;
            }
        }
        __syncthreads();
    }
    unsigned int thr = sel_prefix;

    // ---- deterministic compaction (count -> shfl scan -> write) ----
    int mycnt = 0;
    for (int i = tid; i < CL; i += T1)
        if (f2u(pooled[i] * boost[i / POS]) >= thr) mycnt++;

    int lane = tid & 31, wrp = tid >> 5;
    int v = mycnt;
#pragma unroll
    for (int d = 1; d < 32; d <<= 1) {
        int t = __shfl_up_sync(0xFFFFFFFFu, v, d);
        if (lane >= d) v += t;
    }
    if (lane == 31) s_wsum[wrp] = v;
    __syncthreads();
    if (tid == 0) {
        int a = 0;
        for (int w = 0; w < T1 / 32; w++) { int t = s_wsum[w]; s_wsum[w] = a; a += t; }
        sel_total = a;
    }
    __syncthreads();
    int off = s_wsum[wrp] + v - mycnt;   // exclusive offset, deterministic order
    for (int i = tid; i < CL; i += T1) {
        if (f2u(pooled[i] * boost[i / POS]) >= thr) {
            if (off < CAP) {
                g_idx[b * CAP + off] = (unsigned short)i;
                g_val[b * CAP + off] = pooled[i];
            }
            off++;
        }
    }
    if (tid == 0) g_cnt[b] = sel_total > CAP ? CAP : sel_total;
}

// ================= K2: sparse fc1 (fp16 W) + kwinners(100/1024) + fc2 + lsm ===
#define T2 256

__global__ void __launch_bounds__(T2) k_fc_out(
    const float* __restrict__ fc1_b, const float* __restrict__ duty_fc,
    const float* __restrict__ w2,    const float* __restrict__ b2,
    float* __restrict__ out)
{
    __shared__ float         s_val[CAP];
    __shared__ int           s_idx[CAP];
    __shared__ float         s_h[NFC];
    __shared__ unsigned int  s_keys[NFC];
    __shared__ unsigned int  hist[256];
    __shared__ unsigned int  sel_prefix;
    __shared__ int           sel_kr;
    __shared__ float         s_red[8][10];
    __shared__ float         s_logits[10];
    __shared__ float         s_lse;

    const int tid = threadIdx.x;
    const int b   = blockIdx.x;

    int cnt = g_cnt[b];
    for (int i = tid; i < cnt; i += T2) {
        s_idx[i] = g_idx[b * CAP + i];
        s_val[i] = g_val[b * CAP + i];
    }
    __syncthreads();

    // sparse accumulate: each thread owns 4 output neurons; 8B fp16 loads
    float a0 = 0.f, a1 = 0.f, a2 = 0.f, a3 = 0.f;
    const uint2* __restrict__ W8 = (const uint2*)g_Wh;  // 8B = 4 halfs
#pragma unroll 4
    for (int e = 0; e < cnt; e++) {
        float vv = s_val[e];
        int   j  = s_idx[e];
        uint2 wraw = __ldg(&W8[j * (NFC / 4) + tid]);
        float2 f01 = __half22float2(*(const __half2*)&wraw.x);
        float2 f23 = __half22float2(*(const __half2*)&wraw.y);
        a0 = fmaf(vv, f01.x, a0);
        a1 = fmaf(vv, f01.y, a1);
        a2 = fmaf(vv, f23.x, a2);
        a3 = fmaf(vv, f23.y, a3);
    }

    const float kdn = 100.0f / 1024.0f;
    {
        int n = tid * 4;
        float h0 = a0 + fc1_b[n],     h1 = a1 + fc1_b[n + 1];
        float h2 = a2 + fc1_b[n + 2], h3 = a3 + fc1_b[n + 3];
        s_h[n] = h0; s_h[n + 1] = h1; s_h[n + 2] = h2; s_h[n + 3] = h3;
        s_keys[n]     = f2u(h0 * expf(kdn - duty_fc[n]));
        s_keys[n + 1] = f2u(h1 * expf(kdn - duty_fc[n + 1]));
        s_keys[n + 2] = f2u(h2 * expf(kdn - duty_fc[n + 2]));
        s_keys[n + 3] = f2u(h3 * expf(kdn - duty_fc[n + 3]));
    }
    __syncthreads();

    // radix select: exact 100th largest boosted h
    if (tid == 0) { sel_prefix = 0u; sel_kr = KFC; }
    __syncthreads();
    for (int shift = 24; shift >= 0; shift -= 8) {
        hist[tid] = 0u;
        __syncthreads();
        unsigned int pfx    = sel_prefix;
        unsigned int himask = (shift == 24) ? 0u : (0xFFFFFFFFu << (shift + 8));
#pragma unroll
        for (int q = 0; q < 4; q++) {
            unsigned int u = s_keys[tid * 4 + q];
            if ((u & himask) == pfx) atomicAdd(&hist[(u >> shift) & 255], 1u);
        }
        __syncthreads();
        if (tid == 0) {
            int kk = sel_kr; unsigned int acc = 0;
            for (int bin = 255; bin >= 0; --bin) {
                unsigned int h = hist[bin];
                if (acc + h >= (unsigned)kk) {
                    sel_prefix = pfx | ((unsigned)bin << shift);
                    sel_kr = kk - (int)acc;
                    break;
                }
                acc += h;
            }
        }
        __syncthreads();
    }
    unsigned int thr = sel_prefix;

    // fc2 over winners
    float part[10];
#pragma unroll
    for (int c = 0; c < 10; c++) part[c] = 0.f;
#pragma unroll
    for (int q = 0; q < 4; q++) {
        int n = tid * 4 + q;
        if (s_keys[n] >= thr) {
            float hv = s_h[n];
#pragma unroll
            for (int c = 0; c < 10; c++)
                part[c] = fmaf(hv, w2[c * NFC + n], part[c]);
        }
    }
    int lane = tid & 31, wrp = tid >> 5;
#pragma unroll
    for (int c = 0; c < 10; c++) {
        float pv = part[c];
#pragma unroll
        for (int d = 16; d > 0; d >>= 1)
            pv += __shfl_down_sync(0xFFFFFFFFu, pv, d);
        if (lane == 0) s_red[wrp][c] = pv;
    }
    __syncthreads();
    if (tid < 10) {
        float s = 0.f;
#pragma unroll
        for (int w = 0; w < 8; w++) s += s_red[w][tid];
        s_logits[tid] = s + b2[tid];
    }
    __syncthreads();
    if (tid == 0) {
        float mx = s_logits[0];
        for (int c = 1; c < 10; c++) mx = fmaxf(mx, s_logits[c]);
        float se = 0.f;
        for (int c = 0; c < 10; c++) se += expf(s_logits[c] - mx);
        s_lse = mx + logf(se);
    }
    __syncthreads();
    if (tid < 10) out[b * 10 + tid] = s_logits[tid] - s_lse;
}

// ================= launch =================
extern "C" void kernel_launch(void* const* d_in, const int* in_sizes, int n_in,
                              void* d_out, int out_size)
{
    const float* x        = (const float*)d_in[0];
    const float* c1_w     = (const float*)d_in[1];
    const float* c1_b     = (const float*)d_in[2];
    const float* duty_cnn = (const float*)d_in[3];
    const float* fc1_w    = (const float*)d_in[4];
    const float* fc1_mask = (const float*)d_in[5];
    const float* fc1_b    = (const float*)d_in[6];
    const float* duty_fc  = (const float*)d_in[7];
    const float* fc2_w    = (const float*)d_in[8];
    const float* fc2_b    = (const float*)d_in[9];
    float* out = (float*)d_out;

    k_prep<<<dim3(CL / 32, NFC / 32), dim3(32, 8)>>>(fc1_w, fc1_mask);
    k_conv_pool_kw<<<BATCH, T1>>>(x, c1_w, c1_b, duty_cnn);
    k_fc_out<<<BATCH, T2>>>(fc1_b, duty_fc, fc2_w, fc2_b, out);
}